// round 2
// baseline (speedup 1.0000x reference)
#include <cuda_runtime.h>
#include <cuda_fp16.h>
#include <math.h>

namespace {
constexpr int B_ = 128, S_ = 128, E_ = 256, D_ = 256, O_ = 64;
constexpr int NT = 256;

// dynamic smem layout (bytes)
constexpr int OFF_EP   = 0;                    // float [S_][E_]  131072
constexpr int OFF_X16  = OFF_EP + S_ * E_ * 4; // half  [S_][E_]  65536
constexpr int OFF_H    = OFF_X16 + S_ * E_ * 2;// float [256]
constexpr int OFF_C    = OFF_H + 1024;
constexpr int OFF_HC   = OFF_C + 1024;
constexpr int OFF_CTX  = OFF_HC + 1024;
constexpr int OFF_PART = OFF_CTX + 1024;       // float [4][256]
constexpr int OFF_G    = OFF_PART + 4096;      // float [1024]
constexpr int OFF_SC   = OFF_G + 4096;         // float [128]
constexpr int OFF_Y    = OFF_SC + 512;         // float [64]
constexpr int OFF_YT   = OFF_Y + 256;          // float [64]
constexpr int OFF_W2   = OFF_YT + 256;         // float [256]
constexpr int OFF_RED  = OFF_W2 + 1024;        // float [32]
constexpr int SMEM_BYTES = OFF_RED + 128;      // ~210 KB
}

// scratch for [h_T, context_T] handoff to the output GEMM
__device__ float g_hctx[B_ * (D_ + E_)];

__device__ __forceinline__ float sigm(float x) { return 1.f / (1.f + __expf(-x)); }

__global__ void __launch_bounds__(NT, 1) attn_decoder_kernel(
    const float* __restrict__ x, const float* __restrict__ yh,
    const float* __restrict__ h0, const float* __restrict__ c0,
    const float* __restrict__ W1, const float* __restrict__ b1,
    const float* __restrict__ w2, const float* __restrict__ b2,
    const float* __restrict__ Wih, const float* __restrict__ Whh,
    const float* __restrict__ bih, const float* __restrict__ bhh,
    const float* __restrict__ fcW, const float* __restrict__ fcb)
{
    extern __shared__ char smraw[];
    float*  ep   = (float*)(smraw + OFF_EP);
    __half* x16  = (__half*)(smraw + OFF_X16);
    float*  hsm  = (float*)(smraw + OFF_H);
    float*  csm  = (float*)(smraw + OFF_C);
    float*  hcsm = (float*)(smraw + OFF_HC);
    float*  ctxs = (float*)(smraw + OFF_CTX);
    float*  part = (float*)(smraw + OFF_PART);
    float*  gsm  = (float*)(smraw + OFF_G);
    float*  sc   = (float*)(smraw + OFF_SC);
    float*  ysm  = (float*)(smraw + OFF_Y);
    float*  ytl  = (float*)(smraw + OFF_YT);
    float*  w2s  = (float*)(smraw + OFF_W2);
    float*  red  = (float*)(smraw + OFF_RED);

    const int b    = blockIdx.x;
    const int t    = threadIdx.x;
    const int lane = t & 31, w = t >> 5;
    const int r    = t >> 6, j = t & 63;

    // ---- prologue: stage inputs ----
    const float* xb = x + (size_t)b * S_ * E_;
    for (int i = t; i < S_ * E_; i += NT) x16[i] = __float2half_rn(xb[i]);
    w2s[t] = w2[t];
    hsm[t] = h0[b * D_ + t];
    csm[t] = c0[b * D_ + t];
    const float b2c = b2[0];
    float4 gbias;
    {
        float4 a  = ((const float4*)bih)[t];
        float4 c4 = ((const float4*)bhh)[t];
        gbias = make_float4(a.x + c4.x, a.y + c4.y, a.z + c4.z, a.w + c4.w);
    }
    __syncthreads();

    // ---- enc_proj = x[b] @ We  (We = W1 rows 512..767) ----
    {
        const float4* We4 = (const float4*)(W1 + 2 * D_ * E_);
        for (int s0 = 32 * r; s0 < 32 * r + 32; s0 += 8) {
            float4 acc[8];
            #pragma unroll
            for (int q = 0; q < 8; q++) acc[q] = make_float4(0.f, 0.f, 0.f, 0.f);
            for (int e = 0; e < E_; e++) {
                float4 wv = We4[e * 64 + j];
                #pragma unroll
                for (int q = 0; q < 8; q++) {
                    float xv = __half2float(x16[(s0 + q) * E_ + e]);
                    acc[q].x = fmaf(xv, wv.x, acc[q].x);
                    acc[q].y = fmaf(xv, wv.y, acc[q].y);
                    acc[q].z = fmaf(xv, wv.z, acc[q].z);
                    acc[q].w = fmaf(xv, wv.w, acc[q].w);
                }
            }
            #pragma unroll
            for (int q = 0; q < 8; q++) ((float4*)(ep + (s0 + q) * E_))[j] = acc[q];
        }
    }
    __syncthreads();

    const float4* Wh4  = (const float4*)W1;                // rows 0..255
    const float4* Wc4  = (const float4*)(W1 + D_ * E_);    // rows 256..511
    const float4* Wih4 = (const float4*)Wih;               // [64][1024]
    const float4* Whh4 = (const float4*)Whh;               // [256][1024]

    for (int step = 0; step < S_; step++) {
        // ---- hc = h@Wh + c@Wc + b1 : thread (r,j) does rows 64r..64r+63, cols 4j..4j+3
        {
            float4 acc = make_float4(0.f, 0.f, 0.f, 0.f);
            const int d0 = 64 * r;
            #pragma unroll 4
            for (int d = d0; d < d0 + 64; d++) {
                float  hv = hsm[d], cv = csm[d];
                float4 a  = Wh4[d * 64 + j];
                float4 bb = Wc4[d * 64 + j];
                acc.x = fmaf(hv, a.x, fmaf(cv, bb.x, acc.x));
                acc.y = fmaf(hv, a.y, fmaf(cv, bb.y, acc.y));
                acc.z = fmaf(hv, a.z, fmaf(cv, bb.z, acc.z));
                acc.w = fmaf(hv, a.w, fmaf(cv, bb.w, acc.w));
            }
            ((float4*)(part + r * 256))[j] = acc;
        }
        __syncthreads();
        {
            float v = b1[t];
            #pragma unroll
            for (int rr = 0; rr < 4; rr++) v += part[rr * 256 + t];
            hcsm[t] = v;
            if (t < O_) ysm[t] = yh[((size_t)b * S_ + step) * O_ + t];
        }
        __syncthreads();

        // ---- attention scores: warp w handles s = 16w..16w+15
        {
            #pragma unroll 2
            for (int si = 0; si < 16; si++) {
                int   s   = w * 16 + si;
                float sum = 0.f;
                #pragma unroll
                for (int q = 0; q < 8; q++) {
                    int e = lane + 32 * q;
                    sum = fmaf(tanhf(ep[s * E_ + e] + hcsm[e]), w2s[e], sum);
                }
                #pragma unroll
                for (int off = 16; off; off >>= 1)
                    sum += __shfl_xor_sync(0xffffffffu, sum, off);
                if (lane == 0) sc[s] = sum + b2c;
            }
        }
        __syncthreads();

        // ---- softmax over 128 scores
        {
            float v = (t < S_) ? sc[t] : -1e30f;
            #pragma unroll
            for (int off = 16; off; off >>= 1)
                v = fmaxf(v, __shfl_xor_sync(0xffffffffu, v, off));
            if (lane == 0) red[w] = v;
            __syncthreads();
            if (t == 0) {
                float m = red[0];
                #pragma unroll
                for (int i = 1; i < 8; i++) m = fmaxf(m, red[i]);
                red[16] = m;
            }
            __syncthreads();
            float ex = 0.f;
            if (t < S_) ex = __expf(sc[t] - red[16]);
            float s2 = ex;
            #pragma unroll
            for (int off = 16; off; off >>= 1)
                s2 += __shfl_xor_sync(0xffffffffu, s2, off);
            if (lane == 0) red[w] = s2;
            __syncthreads();
            if (t == 0) {
                float s3 = 0.f;
                #pragma unroll
                for (int i = 0; i < 8; i++) s3 += red[i];
                red[17] = 1.f / s3;
            }
            __syncthreads();
            if (t < S_) sc[t] = ex * red[17];
        }
        __syncthreads();

        // ---- context[e] = sum_s alpha[s] * x[b][s][e]
        {
            float acc = 0.f;
            #pragma unroll 4
            for (int s = 0; s < S_; s++)
                acc = fmaf(sc[s], __half2float(x16[s * E_ + t]), acc);
            ctxs[t] = acc;
        }
        __syncthreads();

        // ---- y_tilde = [ctx; y_t] @ fc_W + fc_b : (r,j) rows 80r..80r+79, col j
        {
            float acc = 0.f;
            const int k0 = 80 * r;
            for (int k = k0; k < k0 + 80; k++) {
                float vv = (k < E_) ? ctxs[k] : ysm[k - E_];
                acc = fmaf(vv, fcW[k * 64 + j], acc);
            }
            part[r * 256 + j] = acc;
        }
        __syncthreads();
        if (t < O_) {
            float v = fcb[t];
            #pragma unroll
            for (int rr = 0; rr < 4; rr++) v += part[rr * 256 + t];
            ytl[t] = v;
        }
        __syncthreads();

        // ---- gates = y_tilde@Wih + h@Whh + biases : thread t owns cols 4t..4t+3
        {
            float4 g = gbias;
            #pragma unroll 4
            for (int k = 0; k < O_; k++) {
                float  yv = ytl[k];
                float4 wv = Wih4[k * 256 + t];
                g.x = fmaf(yv, wv.x, g.x);
                g.y = fmaf(yv, wv.y, g.y);
                g.z = fmaf(yv, wv.z, g.z);
                g.w = fmaf(yv, wv.w, g.w);
            }
            #pragma unroll 4
            for (int k = 0; k < D_; k++) {
                float  hv = hsm[k];
                float4 wv = Whh4[k * 256 + t];
                g.x = fmaf(hv, wv.x, g.x);
                g.y = fmaf(hv, wv.y, g.y);
                g.z = fmaf(hv, wv.z, g.z);
                g.w = fmaf(hv, wv.w, g.w);
            }
            ((float4*)gsm)[t] = g;
        }
        __syncthreads();

        // ---- LSTM pointwise update
        {
            float gi = gsm[t], gf = gsm[256 + t], gg = gsm[512 + t], go = gsm[768 + t];
            float cn = fmaf(sigm(gf), csm[t], sigm(gi) * tanhf(gg));
            float hn = sigm(go) * tanhf(cn);
            hsm[t] = hn;
            csm[t] = cn;
        }
        __syncthreads();
    }

    g_hctx[b * 512 + t]       = hsm[t];
    g_hctx[b * 512 + 256 + t] = ctxs[t];
}

// out[128, 8192] = g_hctx[128,512] @ fc_out_W[512,8192] + b ; block = 128-col tile
__global__ void __launch_bounds__(256, 1) fcout_kernel(
    const float* __restrict__ W, const float* __restrict__ bias,
    float* __restrict__ out)
{
    __shared__ float As[32][128];   // As[kk][row]
    __shared__ float Ws[32][128];   // Ws[kk][col]
    const int n0 = blockIdx.x * 128;
    const int t  = threadIdx.x;
    const int tx = t & 15, ty = t >> 4;

    float acc[8][8];
    #pragma unroll
    for (int i = 0; i < 8; i++)
        #pragma unroll
        for (int jj = 0; jj < 8; jj++) acc[i][jj] = 0.f;

    for (int k0 = 0; k0 < 512; k0 += 32) {
        {
            int q    = t & 7;
            int row0 = t >> 3;
            #pragma unroll
            for (int i = 0; i < 4; i++) {
                int rr = row0 + 32 * i;
                float4 v = *(const float4*)(g_hctx + rr * 512 + k0 + 4 * q);
                As[4 * q + 0][rr] = v.x;
                As[4 * q + 1][rr] = v.y;
                As[4 * q + 2][rr] = v.z;
                As[4 * q + 3][rr] = v.w;
            }
            int nq  = t & 31;
            int kk0 = t >> 5;
            #pragma unroll
            for (int i = 0; i < 4; i++) {
                int kk = kk0 + 8 * i;
                float4 v = *(const float4*)(W + (size_t)(k0 + kk) * 8192 + n0 + 4 * nq);
                *(float4*)(&Ws[kk][4 * nq]) = v;
            }
        }
        __syncthreads();
        #pragma unroll 8
        for (int kk = 0; kk < 32; kk++) {
            float a[8], wv[8];
            #pragma unroll
            for (int i = 0; i < 8; i++) a[i] = As[kk][8 * ty + i];
            #pragma unroll
            for (int i = 0; i < 8; i++) wv[i] = Ws[kk][8 * tx + i];
            #pragma unroll
            for (int i = 0; i < 8; i++)
                #pragma unroll
                for (int jj = 0; jj < 8; jj++)
                    acc[i][jj] = fmaf(a[i], wv[jj], acc[i][jj]);
        }
        __syncthreads();
    }
    #pragma unroll
    for (int i = 0; i < 8; i++) {
        int bb = 8 * ty + i;
        #pragma unroll
        for (int jj = 0; jj < 8; jj++) {
            int n = n0 + 8 * tx + jj;
            out[(size_t)bb * 8192 + n] = acc[i][jj] + bias[n];
        }
    }
}

extern "C" void kernel_launch(void* const* d_in, const int* in_sizes, int n_in,
                              void* d_out, int out_size)
{
    const float* x   = (const float*)d_in[0];
    const float* yh  = (const float*)d_in[1];
    const float* h0  = (const float*)d_in[2];
    const float* c0  = (const float*)d_in[3];
    const float* W1  = (const float*)d_in[4];
    const float* b1  = (const float*)d_in[5];
    const float* w2  = (const float*)d_in[6];
    const float* b2  = (const float*)d_in[7];
    const float* Wih = (const float*)d_in[8];
    const float* Whh = (const float*)d_in[9];
    const float* bih = (const float*)d_in[10];
    const float* bhh = (const float*)d_in[11];
    const float* fcW = (const float*)d_in[12];
    const float* fcb = (const float*)d_in[13];
    const float* foW = (const float*)d_in[14];
    const float* fob = (const float*)d_in[15];

    cudaFuncSetAttribute(attn_decoder_kernel,
                         cudaFuncAttributeMaxDynamicSharedMemorySize, SMEM_BYTES);
    attn_decoder_kernel<<<B_, NT, SMEM_BYTES>>>(x, yh, h0, c0, W1, b1, w2, b2,
                                                Wih, Whh, bih, bhh, fcW, fcb);
    fcout_kernel<<<64, 256>>>(foW, fob, (float*)d_out);
}

// round 3
// speedup vs baseline: 1.0121x; 1.0121x over previous
#include <cuda_runtime.h>
#include <cuda_fp16.h>
#include <math.h>

namespace {
constexpr int B_ = 128, S_ = 128, E_ = 256, D_ = 256, O_ = 64;
constexpr int NT = 256;

// dynamic smem layout (bytes)
constexpr int OFF_EP   = 0;                    // float [S_][E_]  131072
constexpr int OFF_X16  = OFF_EP + S_ * E_ * 4; // half  [S_][E_]  65536
constexpr int OFF_H    = OFF_X16 + S_ * E_ * 2;// float [256]
constexpr int OFF_C    = OFF_H + 1024;
constexpr int OFF_HC   = OFF_C + 1024;
constexpr int OFF_CTX  = OFF_HC + 1024;
constexpr int OFF_PART = OFF_CTX + 1024;       // float [4][256]
constexpr int OFF_G    = OFF_PART + 4096;      // float [1024]
constexpr int OFF_SC   = OFF_G + 4096;         // float [128]
constexpr int OFF_Y    = OFF_SC + 512;         // float [64]
constexpr int OFF_YT   = OFF_Y + 256;          // float [64]
constexpr int OFF_W2   = OFF_YT + 256;         // float [256]
constexpr int OFF_RED  = OFF_W2 + 1024;        // float [32]
constexpr int SMEM_BYTES = OFF_RED + 128;      // ~210 KB
}

// fp16 weight copies (converted once per launch)
__device__ __half2 g_whc[D_ * E_];        // [d][c] = (Wh[d][c], Wc[d][c])
__device__ __half  g_whh[D_ * 4 * D_];    // [256][1024]
__device__ __half  g_wih[O_ * 4 * D_];    // [64][1024]
__device__ __half  g_fcw[(E_ + O_) * O_]; // [320][64]
// scratch for [h_T, context_T] handoff to the output GEMM
__device__ float g_hctx[B_ * (D_ + E_)];

__device__ __forceinline__ float sigm_f(float x) {
    float e = __expf(-x);
    return __fdividef(1.f, 1.f + e);
}
__device__ __forceinline__ float tanh_f(float x) {
    float e = __expf(2.f * x);
    return 1.f - __fdividef(2.f, e + 1.f);
}

__global__ void __launch_bounds__(256) convert_weights_kernel(
    const float* __restrict__ W1, const float* __restrict__ Whh,
    const float* __restrict__ Wih, const float* __restrict__ fcW)
{
    int i = blockIdx.x * 256 + threadIdx.x;
    if (i < D_ * E_) {
        int d = i >> 8, c = i & 255;
        g_whc[i] = __floats2half2_rn(W1[d * E_ + c], W1[(D_ + d) * E_ + c]);
    }
    if (i < D_ * 4 * D_)      g_whh[i] = __float2half_rn(Whh[i]);
    if (i < O_ * 4 * D_)      g_wih[i] = __float2half_rn(Wih[i]);
    if (i < (E_ + O_) * O_)   g_fcw[i] = __float2half_rn(fcW[i]);
}

__global__ void __launch_bounds__(NT, 1) attn_decoder_kernel(
    const float* __restrict__ x, const float* __restrict__ yh,
    const float* __restrict__ h0, const float* __restrict__ c0,
    const float* __restrict__ W1, const float* __restrict__ b1,
    const float* __restrict__ w2, const float* __restrict__ b2,
    const float* __restrict__ bih, const float* __restrict__ bhh,
    const float* __restrict__ fcb)
{
    extern __shared__ char smraw[];
    float*  ep   = (float*)(smraw + OFF_EP);
    __half* x16  = (__half*)(smraw + OFF_X16);
    float*  hsm  = (float*)(smraw + OFF_H);
    float*  csm  = (float*)(smraw + OFF_C);
    float*  hcsm = (float*)(smraw + OFF_HC);
    float*  ctxs = (float*)(smraw + OFF_CTX);
    float*  part = (float*)(smraw + OFF_PART);
    float*  gsm  = (float*)(smraw + OFF_G);
    float*  sc   = (float*)(smraw + OFF_SC);
    float*  ysm  = (float*)(smraw + OFF_Y);
    float*  ytl  = (float*)(smraw + OFF_YT);
    float*  w2s  = (float*)(smraw + OFF_W2);
    float*  red  = (float*)(smraw + OFF_RED);

    const int b    = blockIdx.x;
    const int t    = threadIdx.x;
    const int lane = t & 31, w = t >> 5;
    const int r    = t >> 6, j = t & 63;

    // ---- prologue: stage inputs ----
    const float* xb = x + (size_t)b * S_ * E_;
    for (int i = t; i < S_ * E_; i += NT) x16[i] = __float2half_rn(xb[i]);
    w2s[t] = w2[t];
    hsm[t] = h0[b * D_ + t];
    csm[t] = c0[b * D_ + t];
    const float b2c = b2[0];
    float4 gbias;
    {
        float4 a  = ((const float4*)bih)[t];
        float4 c4 = ((const float4*)bhh)[t];
        gbias = make_float4(a.x + c4.x, a.y + c4.y, a.z + c4.z, a.w + c4.w);
    }
    __syncthreads();

    // ---- enc_proj = x[b] @ We  (We = W1 rows 512..767, fp32 one-time) ----
    {
        const float4* We4 = (const float4*)(W1 + 2 * D_ * E_);
        for (int s0 = 32 * r; s0 < 32 * r + 32; s0 += 8) {
            float4 acc[8];
            #pragma unroll
            for (int q = 0; q < 8; q++) acc[q] = make_float4(0.f, 0.f, 0.f, 0.f);
            for (int e = 0; e < E_; e++) {
                float4 wv = We4[e * 64 + j];
                #pragma unroll
                for (int q = 0; q < 8; q++) {
                    float xv = __half2float(x16[(s0 + q) * E_ + e]);
                    acc[q].x = fmaf(xv, wv.x, acc[q].x);
                    acc[q].y = fmaf(xv, wv.y, acc[q].y);
                    acc[q].z = fmaf(xv, wv.z, acc[q].z);
                    acc[q].w = fmaf(xv, wv.w, acc[q].w);
                }
            }
            #pragma unroll
            for (int q = 0; q < 8; q++) ((float4*)(ep + (s0 + q) * E_))[j] = acc[q];
        }
    }
    __syncthreads();

    const uint4* whc4 = (const uint4*)g_whc;   // [d][4 cols] as 4×half2
    const uint2* wih2 = (const uint2*)g_wih;   // [k][4 cols] as 2×half2
    const uint2* whh2 = (const uint2*)g_whh;

    for (int step = 0; step < S_; step++) {
        // ---- hc = h@Wh + c@Wc + b1 : thread (r,j) rows 64r..64r+63, cols 4j..4j+3
        {
            float4 acc = make_float4(0.f, 0.f, 0.f, 0.f);
            const int d0 = 64 * r;
            #pragma unroll 4
            for (int d = d0; d < d0 + 64; d++) {
                float hv = hsm[d], cv = csm[d];
                uint4 v = whc4[d * 64 + j];
                float2 p;
                p = __half22float2(*(__half2*)&v.x);
                acc.x = fmaf(hv, p.x, fmaf(cv, p.y, acc.x));
                p = __half22float2(*(__half2*)&v.y);
                acc.y = fmaf(hv, p.x, fmaf(cv, p.y, acc.y));
                p = __half22float2(*(__half2*)&v.z);
                acc.z = fmaf(hv, p.x, fmaf(cv, p.y, acc.z));
                p = __half22float2(*(__half2*)&v.w);
                acc.w = fmaf(hv, p.x, fmaf(cv, p.y, acc.w));
            }
            ((float4*)(part + r * 256))[j] = acc;
        }
        __syncthreads();
        {
            float v = b1[t];
            #pragma unroll
            for (int rr = 0; rr < 4; rr++) v += part[rr * 256 + t];
            hcsm[t] = v;
            if (t < O_) ysm[t] = yh[((size_t)b * S_ + step) * O_ + t];
        }
        __syncthreads();

        // ---- attention scores: warp w handles s = 16w..16w+15
        {
            #pragma unroll 2
            for (int si = 0; si < 16; si++) {
                int   s   = w * 16 + si;
                float sum = 0.f;
                #pragma unroll
                for (int q = 0; q < 8; q++) {
                    int e = lane + 32 * q;
                    sum = fmaf(tanh_f(ep[s * E_ + e] + hcsm[e]), w2s[e], sum);
                }
                #pragma unroll
                for (int off = 16; off; off >>= 1)
                    sum += __shfl_xor_sync(0xffffffffu, sum, off);
                if (lane == 0) sc[s] = sum + b2c;
            }
        }
        __syncthreads();

        // ---- softmax over 128 scores
        {
            float v = (t < S_) ? sc[t] : -1e30f;
            #pragma unroll
            for (int off = 16; off; off >>= 1)
                v = fmaxf(v, __shfl_xor_sync(0xffffffffu, v, off));
            if (lane == 0) red[w] = v;
            __syncthreads();
            if (t == 0) {
                float m = red[0];
                #pragma unroll
                for (int i = 1; i < 8; i++) m = fmaxf(m, red[i]);
                red[16] = m;
            }
            __syncthreads();
            float ex = 0.f;
            if (t < S_) ex = __expf(sc[t] - red[16]);
            float s2 = ex;
            #pragma unroll
            for (int off = 16; off; off >>= 1)
                s2 += __shfl_xor_sync(0xffffffffu, s2, off);
            if (lane == 0) red[w] = s2;
            __syncthreads();
            if (t == 0) {
                float s3 = 0.f;
                #pragma unroll
                for (int i = 0; i < 8; i++) s3 += red[i];
                red[17] = __fdividef(1.f, s3);
            }
            __syncthreads();
            if (t < S_) sc[t] = ex * red[17];
        }
        __syncthreads();

        // ---- context[e] = sum_s alpha[s] * x[b][s][e]
        {
            float acc = 0.f;
            #pragma unroll 4
            for (int s = 0; s < S_; s++)
                acc = fmaf(sc[s], __half2float(x16[s * E_ + t]), acc);
            ctxs[t] = acc;
        }
        __syncthreads();

        // ---- y_tilde = [ctx; y_t] @ fc_W + fc_b : (r,j) rows 80r..80r+79, col j
        {
            float acc = 0.f;
            const int k0 = 80 * r;
            for (int k = k0; k < k0 + 80; k++) {
                float vv = (k < E_) ? ctxs[k] : ysm[k - E_];
                acc = fmaf(vv, __half2float(g_fcw[k * 64 + j]), acc);
            }
            part[r * 256 + j] = acc;
        }
        __syncthreads();
        if (t < O_) {
            float v = fcb[t];
            #pragma unroll
            for (int rr = 0; rr < 4; rr++) v += part[rr * 256 + t];
            ytl[t] = v;
        }
        __syncthreads();

        // ---- gates = y_tilde@Wih + h@Whh + biases : thread t owns cols 4t..4t+3
        {
            float4 g = gbias;
            #pragma unroll 4
            for (int k = 0; k < O_; k++) {
                float yv = ytl[k];
                uint2 v = wih2[k * 256 + t];
                float2 a  = __half22float2(*(__half2*)&v.x);
                float2 bb = __half22float2(*(__half2*)&v.y);
                g.x = fmaf(yv, a.x, g.x);
                g.y = fmaf(yv, a.y, g.y);
                g.z = fmaf(yv, bb.x, g.z);
                g.w = fmaf(yv, bb.y, g.w);
            }
            #pragma unroll 4
            for (int k = 0; k < D_; k++) {
                float hv = hsm[k];
                uint2 v = whh2[k * 256 + t];
                float2 a  = __half22float2(*(__half2*)&v.x);
                float2 bb = __half22float2(*(__half2*)&v.y);
                g.x = fmaf(hv, a.x, g.x);
                g.y = fmaf(hv, a.y, g.y);
                g.z = fmaf(hv, bb.x, g.z);
                g.w = fmaf(hv, bb.y, g.w);
            }
            ((float4*)gsm)[t] = g;
        }
        __syncthreads();

        // ---- LSTM pointwise update
        {
            float gi = gsm[t], gf = gsm[256 + t], gg = gsm[512 + t], go = gsm[768 + t];
            float cn = fmaf(sigm_f(gf), csm[t], sigm_f(gi) * tanh_f(gg));
            float hn = sigm_f(go) * tanh_f(cn);
            hsm[t] = hn;
            csm[t] = cn;
        }
        __syncthreads();
    }

    g_hctx[b * 512 + t]       = hsm[t];
    g_hctx[b * 512 + 256 + t] = ctxs[t];
}

// out[128, 8192] = g_hctx[128,512] @ fc_out_W[512,8192] + b ; block = 128-col tile
__global__ void __launch_bounds__(256, 1) fcout_kernel(
    const float* __restrict__ W, const float* __restrict__ bias,
    float* __restrict__ out)
{
    __shared__ float As[32][128];   // As[kk][row]
    __shared__ float Ws[32][128];   // Ws[kk][col]
    const int n0 = blockIdx.x * 128;
    const int t  = threadIdx.x;
    const int tx = t & 15, ty = t >> 4;

    float acc[8][8];
    #pragma unroll
    for (int i = 0; i < 8; i++)
        #pragma unroll
        for (int jj = 0; jj < 8; jj++) acc[i][jj] = 0.f;

    for (int k0 = 0; k0 < 512; k0 += 32) {
        {
            int q    = t & 7;
            int row0 = t >> 3;
            #pragma unroll
            for (int i = 0; i < 4; i++) {
                int rr = row0 + 32 * i;
                float4 v = *(const float4*)(g_hctx + rr * 512 + k0 + 4 * q);
                As[4 * q + 0][rr] = v.x;
                As[4 * q + 1][rr] = v.y;
                As[4 * q + 2][rr] = v.z;
                As[4 * q + 3][rr] = v.w;
            }
            int nq  = t & 31;
            int kk0 = t >> 5;
            #pragma unroll
            for (int i = 0; i < 4; i++) {
                int kk = kk0 + 8 * i;
                float4 v = *(const float4*)(W + (size_t)(k0 + kk) * 8192 + n0 + 4 * nq);
                *(float4*)(&Ws[kk][4 * nq]) = v;
            }
        }
        __syncthreads();
        #pragma unroll 8
        for (int kk = 0; kk < 32; kk++) {
            float a[8], wv[8];
            #pragma unroll
            for (int i = 0; i < 8; i++) a[i] = As[kk][8 * ty + i];
            #pragma unroll
            for (int i = 0; i < 8; i++) wv[i] = Ws[kk][8 * tx + i];
            #pragma unroll
            for (int i = 0; i < 8; i++)
                #pragma unroll
                for (int jj = 0; jj < 8; jj++)
                    acc[i][jj] = fmaf(a[i], wv[jj], acc[i][jj]);
        }
        __syncthreads();
    }
    #pragma unroll
    for (int i = 0; i < 8; i++) {
        int bb = 8 * ty + i;
        #pragma unroll
        for (int jj = 0; jj < 8; jj++) {
            int n = n0 + 8 * tx + jj;
            out[(size_t)bb * 8192 + n] = acc[i][jj] + bias[n];
        }
    }
}

extern "C" void kernel_launch(void* const* d_in, const int* in_sizes, int n_in,
                              void* d_out, int out_size)
{
    const float* x   = (const float*)d_in[0];
    const float* yh  = (const float*)d_in[1];
    const float* h0  = (const float*)d_in[2];
    const float* c0  = (const float*)d_in[3];
    const float* W1  = (const float*)d_in[4];
    const float* b1  = (const float*)d_in[5];
    const float* w2  = (const float*)d_in[6];
    const float* b2  = (const float*)d_in[7];
    const float* Wih = (const float*)d_in[8];
    const float* Whh = (const float*)d_in[9];
    const float* bih = (const float*)d_in[10];
    const float* bhh = (const float*)d_in[11];
    const float* fcW = (const float*)d_in[12];
    const float* fcb = (const float*)d_in[13];
    const float* foW = (const float*)d_in[14];
    const float* fob = (const float*)d_in[15];

    convert_weights_kernel<<<(D_ * 4 * D_ + 255) / 256, 256>>>(W1, Whh, Wih, fcW);

    cudaFuncSetAttribute(attn_decoder_kernel,
                         cudaFuncAttributeMaxDynamicSharedMemorySize, SMEM_BYTES);
    attn_decoder_kernel<<<B_, NT, SMEM_BYTES>>>(x, yh, h0, c0, W1, b1, w2, b2,
                                                bih, bhh, fcb);
    fcout_kernel<<<64, 256>>>(foW, fob, (float*)d_out);
}

// round 4
// speedup vs baseline: 1.3435x; 1.3275x over previous
#include <cuda_runtime.h>
#include <cuda_fp16.h>
#include <math.h>

namespace {
constexpr int B_ = 128, S_ = 128, E_ = 256, D_ = 256, O_ = 64;
constexpr int NT = 512;

// dynamic smem layout (bytes)
constexpr int OFF_EP   = 0;                      // float [128][256] 131072
constexpr int OFF_X16  = OFF_EP + S_ * E_ * 4;   // half  [128][256] 65536
constexpr int OFF_H    = OFF_X16 + S_ * E_ * 2;  // float [256]
constexpr int OFF_C    = OFF_H + 1024;
constexpr int OFF_HC   = OFF_C + 1024;
constexpr int OFF_CTX  = OFF_HC + 1024;
constexpr int OFF_PART = OFF_CTX + 1024;         // float [8][256] 8192
constexpr int OFF_G    = OFF_PART + 8192;        // float [2][1024] 8192
constexpr int OFF_SC   = OFF_G + 8192;           // float [128]
constexpr int OFF_Y    = OFF_SC + 512;           // float [64]
constexpr int OFF_YT   = OFF_Y + 256;            // float [64]
constexpr int OFF_W2   = OFF_YT + 256;           // float [256]
constexpr int OFF_RED  = OFF_W2 + 1024;          // float [32]
constexpr int SMEM_BYTES = OFF_RED + 128;        // ~214 KB
}

// fp16 weight copies (converted once per launch)
__device__ __half2 g_whc[D_ * E_];        // [d][c] = (Wh[d][c], Wc[d][c])
__device__ __half  g_whh[D_ * 4 * D_];    // [256][1024]
__device__ __half  g_wih[O_ * 4 * D_];    // [64][1024]
__device__ __half  g_fcw[(E_ + O_) * O_]; // [320][64]
__device__ float   g_hctx[B_ * (D_ + E_)];

__device__ __forceinline__ float sigm_f(float x) {
    float e = __expf(-x);
    return __fdividef(1.f, 1.f + e);
}
__device__ __forceinline__ float tanh_f(float x) {
    float e = __expf(2.f * x);
    return 1.f - __fdividef(2.f, e + 1.f);
}

__global__ void __launch_bounds__(256) convert_weights_kernel(
    const float* __restrict__ W1, const float* __restrict__ Whh,
    const float* __restrict__ Wih, const float* __restrict__ fcW)
{
    int i = blockIdx.x * 256 + threadIdx.x;
    if (i < D_ * E_) {
        int d = i >> 8, c = i & 255;
        g_whc[i] = __floats2half2_rn(W1[d * E_ + c], W1[(D_ + d) * E_ + c]);
    }
    if (i < D_ * 4 * D_)      g_whh[i] = __float2half_rn(Whh[i]);
    if (i < O_ * 4 * D_)      g_wih[i] = __float2half_rn(Wih[i]);
    if (i < (E_ + O_) * O_)   g_fcw[i] = __float2half_rn(fcW[i]);
}

__global__ void __launch_bounds__(NT, 1) attn_decoder_kernel(
    const float* __restrict__ x, const float* __restrict__ yh,
    const float* __restrict__ h0, const float* __restrict__ c0,
    const float* __restrict__ W1, const float* __restrict__ b1,
    const float* __restrict__ w2, const float* __restrict__ b2,
    const float* __restrict__ bih, const float* __restrict__ bhh,
    const float* __restrict__ fcb)
{
    extern __shared__ char smraw[];
    float*  ep   = (float*)(smraw + OFF_EP);
    __half* x16  = (__half*)(smraw + OFF_X16);
    float*  hsm  = (float*)(smraw + OFF_H);
    float*  csm  = (float*)(smraw + OFF_C);
    float*  hcsm = (float*)(smraw + OFF_HC);
    float*  ctxs = (float*)(smraw + OFF_CTX);
    float*  part = (float*)(smraw + OFF_PART);
    float*  gsm  = (float*)(smraw + OFF_G);
    float*  sc   = (float*)(smraw + OFF_SC);
    float*  ysm  = (float*)(smraw + OFF_Y);
    float*  ytl  = (float*)(smraw + OFF_YT);
    float*  w2s  = (float*)(smraw + OFF_W2);
    float*  red  = (float*)(smraw + OFF_RED);

    const int b    = blockIdx.x;
    const int t    = threadIdx.x;
    const int lane = t & 31, w = t >> 5;
    const int r    = t >> 6, j = t & 63;   // 8 groups x 64

    // ---- prologue ----
    const float* xb = x + (size_t)b * S_ * E_;
    for (int i = t; i < S_ * E_; i += NT) x16[i] = __float2half_rn(xb[i]);
    if (t < 256) {
        w2s[t] = w2[t];
        hsm[t] = h0[b * D_ + t];
        csm[t] = c0[b * D_ + t];
    }
    const float b2c = b2[0];
    float4 gbias = make_float4(0.f, 0.f, 0.f, 0.f);
    if (t < 256) {
        float4 a  = ((const float4*)bih)[t];
        float4 c4 = ((const float4*)bhh)[t];
        gbias = make_float4(a.x + c4.x, a.y + c4.y, a.z + c4.z, a.w + c4.w);
    }
    __syncthreads();

    // ---- enc_proj = x[b] @ We  (one-time, fp32 weights) ----
    {
        const float4* We4 = (const float4*)(W1 + 2 * D_ * E_);
        for (int s0 = 16 * r; s0 < 16 * r + 16; s0 += 8) {
            float4 acc[8];
            #pragma unroll
            for (int q = 0; q < 8; q++) acc[q] = make_float4(0.f, 0.f, 0.f, 0.f);
            for (int e = 0; e < E_; e++) {
                float4 wv = We4[e * 64 + j];
                #pragma unroll
                for (int q = 0; q < 8; q++) {
                    float xv = __half2float(x16[(s0 + q) * E_ + e]);
                    acc[q].x = fmaf(xv, wv.x, acc[q].x);
                    acc[q].y = fmaf(xv, wv.y, acc[q].y);
                    acc[q].z = fmaf(xv, wv.z, acc[q].z);
                    acc[q].w = fmaf(xv, wv.w, acc[q].w);
                }
            }
            #pragma unroll
            for (int q = 0; q < 8; q++) ((float4*)(ep + (s0 + q) * E_))[j] = acc[q];
        }
    }
    __syncthreads();

    const uint4* whc4 = (const uint4*)g_whc;
    const uint2* wih2 = (const uint2*)g_wih;
    const uint2* whh2 = (const uint2*)g_whh;
    const int kh = t >> 8;     // 0/1: k-split for gates & context
    const int cg = t & 255;    // col group for gates / e for context

    for (int step = 0; step < S_; step++) {
        // ---- hc partial: thread (r,j): rows 32r..32r+31, cols 4j..4j+3 ----
        {
            float4 acc = make_float4(0.f, 0.f, 0.f, 0.f);
            const int d0 = 32 * r;
            #pragma unroll
            for (int kk = 0; kk < 32; kk += 8) {
                uint4 v[8];
                #pragma unroll
                for (int q = 0; q < 8; q++) v[q] = whc4[(d0 + kk + q) * 64 + j];
                #pragma unroll
                for (int q = 0; q < 8; q++) {
                    float hv = hsm[d0 + kk + q], cv = csm[d0 + kk + q];
                    float2 p;
                    p = __half22float2(*(__half2*)&v[q].x);
                    acc.x = fmaf(hv, p.x, fmaf(cv, p.y, acc.x));
                    p = __half22float2(*(__half2*)&v[q].y);
                    acc.y = fmaf(hv, p.x, fmaf(cv, p.y, acc.y));
                    p = __half22float2(*(__half2*)&v[q].z);
                    acc.z = fmaf(hv, p.x, fmaf(cv, p.y, acc.z));
                    p = __half22float2(*(__half2*)&v[q].w);
                    acc.w = fmaf(hv, p.x, fmaf(cv, p.y, acc.w));
                }
            }
            ((float4*)(part + r * 256))[j] = acc;
        }
        __syncthreads();
        if (t < 256) {
            float v = b1[t];
            #pragma unroll
            for (int rr = 0; rr < 8; rr++) v += part[rr * 256 + t];
            hcsm[t] = v;
        } else if (t < 256 + O_) {
            ysm[t - 256] = yh[((size_t)b * S_ + step) * O_ + (t - 256)];
        }
        __syncthreads();

        // ---- attention scores: warp w handles s = 8w..8w+7 ----
        {
            #pragma unroll 2
            for (int si = 0; si < 8; si++) {
                int   s   = w * 8 + si;
                float sum = 0.f;
                #pragma unroll
                for (int q = 0; q < 8; q++) {
                    int e = lane + 32 * q;
                    sum = fmaf(tanh_f(ep[s * E_ + e] + hcsm[e]), w2s[e], sum);
                }
                #pragma unroll
                for (int off = 16; off; off >>= 1)
                    sum += __shfl_xor_sync(0xffffffffu, sum, off);
                if (lane == 0) sc[s] = sum + b2c;
            }
        }
        __syncthreads();

        // ---- softmax over 128 scores (warps 0..3) ----
        {
            float ex = 0.f;
            if (t < 128) {
                float v = sc[t];
                #pragma unroll
                for (int off = 16; off; off >>= 1)
                    v = fmaxf(v, __shfl_xor_sync(0xffffffffu, v, off));
                if (lane == 0) red[w] = v;
            }
            __syncthreads();
            if (t == 0)
                red[16] = fmaxf(fmaxf(red[0], red[1]), fmaxf(red[2], red[3]));
            __syncthreads();
            if (t < 128) {
                ex = __expf(sc[t] - red[16]);
                float s2 = ex;
                #pragma unroll
                for (int off = 16; off; off >>= 1)
                    s2 += __shfl_xor_sync(0xffffffffu, s2, off);
                if (lane == 0) red[w] = s2;
            }
            __syncthreads();
            if (t == 0)
                red[17] = __fdividef(1.f, red[0] + red[1] + red[2] + red[3]);
            __syncthreads();
            if (t < 128) sc[t] = ex * red[17];
        }
        __syncthreads();

        // ---- context: split over s halves ----
        {
            float acc = 0.f;
            const int s0 = 64 * kh;
            #pragma unroll 8
            for (int s = s0; s < s0 + 64; s++)
                acc = fmaf(sc[s], __half2float(x16[s * E_ + cg]), acc);
            part[kh * 256 + cg] = acc;
        }
        __syncthreads();
        if (t < 256) ctxs[t] = part[t] + part[256 + t];
        __syncthreads();

        // ---- y_tilde = [ctx; y_t] @ fc_W : thread (r,j) k in [40r,40r+40), col j
        {
            float acc = 0.f;
            const int k0 = 40 * r;
            #pragma unroll 8
            for (int k = k0; k < k0 + 40; k++) {
                float vv = (k < E_) ? ctxs[k] : ysm[k - E_];
                acc = fmaf(vv, __half2float(g_fcw[k * 64 + j]), acc);
            }
            part[r * 256 + j] = acc;
        }
        __syncthreads();
        if (t < O_) {
            float v = fcb[t];
            #pragma unroll
            for (int rr = 0; rr < 8; rr++) v += part[rr * 256 + t];
            ytl[t] = v;
        }
        __syncthreads();

        // ---- gates: k-split halves; thread owns cols 4cg..4cg+3, half kh ----
        {
            float4 g = make_float4(0.f, 0.f, 0.f, 0.f);
            if (kh == 0) {
                // Wih rows 0..63
                #pragma unroll
                for (int k0 = 0; k0 < 64; k0 += 8) {
                    uint2 v[8];
                    #pragma unroll
                    for (int q = 0; q < 8; q++) v[q] = wih2[(k0 + q) * 256 + cg];
                    #pragma unroll
                    for (int q = 0; q < 8; q++) {
                        float yv = ytl[k0 + q];
                        float2 a  = __half22float2(*(__half2*)&v[q].x);
                        float2 bb = __half22float2(*(__half2*)&v[q].y);
                        g.x = fmaf(yv, a.x, g.x);
                        g.y = fmaf(yv, a.y, g.y);
                        g.z = fmaf(yv, bb.x, g.z);
                        g.w = fmaf(yv, bb.y, g.w);
                    }
                }
                // Whh rows 0..95
                #pragma unroll 2
                for (int k0 = 0; k0 < 96; k0 += 8) {
                    uint2 v[8];
                    #pragma unroll
                    for (int q = 0; q < 8; q++) v[q] = whh2[(k0 + q) * 256 + cg];
                    #pragma unroll
                    for (int q = 0; q < 8; q++) {
                        float hv = hsm[k0 + q];
                        float2 a  = __half22float2(*(__half2*)&v[q].x);
                        float2 bb = __half22float2(*(__half2*)&v[q].y);
                        g.x = fmaf(hv, a.x, g.x);
                        g.y = fmaf(hv, a.y, g.y);
                        g.z = fmaf(hv, bb.x, g.z);
                        g.w = fmaf(hv, bb.y, g.w);
                    }
                }
            } else {
                // Whh rows 96..255
                #pragma unroll 2
                for (int k0 = 96; k0 < 256; k0 += 8) {
                    uint2 v[8];
                    #pragma unroll
                    for (int q = 0; q < 8; q++) v[q] = whh2[(k0 + q) * 256 + cg];
                    #pragma unroll
                    for (int q = 0; q < 8; q++) {
                        float hv = hsm[k0 + q];
                        float2 a  = __half22float2(*(__half2*)&v[q].x);
                        float2 bb = __half22float2(*(__half2*)&v[q].y);
                        g.x = fmaf(hv, a.x, g.x);
                        g.y = fmaf(hv, a.y, g.y);
                        g.z = fmaf(hv, bb.x, g.z);
                        g.w = fmaf(hv, bb.y, g.w);
                    }
                }
            }
            ((float4*)(gsm + kh * 1024))[cg] = g;
        }
        __syncthreads();
        if (t < 256) {
            float4 a  = ((float4*)gsm)[t];
            float4 b4 = ((float4*)(gsm + 1024))[t];
            a.x += b4.x + gbias.x;
            a.y += b4.y + gbias.y;
            a.z += b4.z + gbias.z;
            a.w += b4.w + gbias.w;
            ((float4*)gsm)[t] = a;
        }
        __syncthreads();
        if (t < 256) {
            float gi = gsm[t], gf = gsm[256 + t], gg = gsm[512 + t], go = gsm[768 + t];
            float cn = fmaf(sigm_f(gf), csm[t], sigm_f(gi) * tanh_f(gg));
            float hn = sigm_f(go) * tanh_f(cn);
            hsm[t] = hn;
            csm[t] = cn;
        }
        __syncthreads();
    }

    if (t < 256) {
        g_hctx[b * 512 + t]       = hsm[t];
        g_hctx[b * 512 + 256 + t] = ctxs[t];
    }
}

// out[128, 8192] = g_hctx[128,512] @ fc_out_W[512,8192] + b ; 128 blocks, 64-col tiles
__global__ void __launch_bounds__(256, 1) fcout_kernel(
    const float* __restrict__ W, const float* __restrict__ bias,
    float* __restrict__ out)
{
    __shared__ float As[32][128];
    __shared__ float Ws[32][64];
    const int n0 = blockIdx.x * 64;
    const int t  = threadIdx.x;
    const int tx = t & 7, ty = t >> 3;   // cols 8tx.., rows 4ty..

    float bv[8];
    #pragma unroll
    for (int jj = 0; jj < 8; jj++) bv[jj] = bias[n0 + 8 * tx + jj];

    float acc[4][8];
    #pragma unroll
    for (int i = 0; i < 4; i++)
        #pragma unroll
        for (int jj = 0; jj < 8; jj++) acc[i][jj] = 0.f;

    for (int k0 = 0; k0 < 512; k0 += 32) {
        {
            int q    = t & 7;
            int row0 = t >> 3;
            #pragma unroll
            for (int i = 0; i < 4; i++) {
                int rr = row0 + 32 * i;
                float4 v = *(const float4*)(g_hctx + rr * 512 + k0 + 4 * q);
                As[4 * q + 0][rr] = v.x;
                As[4 * q + 1][rr] = v.y;
                As[4 * q + 2][rr] = v.z;
                As[4 * q + 3][rr] = v.w;
            }
            int nq  = t & 15;
            int kk0 = t >> 4;
            #pragma unroll
            for (int i = 0; i < 2; i++) {
                int kk = kk0 + 16 * i;
                float4 v = *(const float4*)(W + (size_t)(k0 + kk) * 8192 + n0 + 4 * nq);
                *(float4*)(&Ws[kk][4 * nq]) = v;
            }
        }
        __syncthreads();
        #pragma unroll 8
        for (int kk = 0; kk < 32; kk++) {
            float a[4], wv[8];
            #pragma unroll
            for (int i = 0; i < 4; i++) a[i] = As[kk][4 * ty + i];
            #pragma unroll
            for (int jj = 0; jj < 8; jj++) wv[jj] = Ws[kk][8 * tx + jj];
            #pragma unroll
            for (int i = 0; i < 4; i++)
                #pragma unroll
                for (int jj = 0; jj < 8; jj++)
                    acc[i][jj] = fmaf(a[i], wv[jj], acc[i][jj]);
        }
        __syncthreads();
    }
    #pragma unroll
    for (int i = 0; i < 4; i++) {
        int bb = 4 * ty + i;
        #pragma unroll
        for (int jj = 0; jj < 8; jj++)
            out[(size_t)bb * 8192 + n0 + 8 * tx + jj] = acc[i][jj] + bv[jj];
    }
}

extern "C" void kernel_launch(void* const* d_in, const int* in_sizes, int n_in,
                              void* d_out, int out_size)
{
    const float* x   = (const float*)d_in[0];
    const float* yh  = (const float*)d_in[1];
    const float* h0  = (const float*)d_in[2];
    const float* c0  = (const float*)d_in[3];
    const float* W1  = (const float*)d_in[4];
    const float* b1  = (const float*)d_in[5];
    const float* w2  = (const float*)d_in[6];
    const float* b2  = (const float*)d_in[7];
    const float* Wih = (const float*)d_in[8];
    const float* Whh = (const float*)d_in[9];
    const float* bih = (const float*)d_in[10];
    const float* bhh = (const float*)d_in[11];
    const float* fcW = (const float*)d_in[12];
    const float* fcb = (const float*)d_in[13];
    const float* foW = (const float*)d_in[14];
    const float* fob = (const float*)d_in[15];

    convert_weights_kernel<<<(D_ * 4 * D_ + 255) / 256, 256>>>(W1, Whh, Wih, fcW);

    cudaFuncSetAttribute(attn_decoder_kernel,
                         cudaFuncAttributeMaxDynamicSharedMemorySize, SMEM_BYTES);
    attn_decoder_kernel<<<B_, NT, SMEM_BYTES>>>(x, yh, h0, c0, W1, b1, w2, b2,
                                                bih, bhh, fcb);
    fcout_kernel<<<128, 256>>>(foW, fob, (float*)d_out);
}

// round 5
// speedup vs baseline: 1.8520x; 1.3784x over previous
#include <cuda_runtime.h>
#include <cuda_fp16.h>
#include <math.h>

namespace {
constexpr int B_ = 128, S_ = 128, E_ = 256, D_ = 256, O_ = 64;
constexpr int NT = 512;

// dynamic smem layout (bytes)
constexpr int OFF_EP   = 0;                 // float [128][256] 131072
constexpr int OFF_X16  = 131072;            // half  [128][256]  65536
constexpr int OFF_GS   = 196608;            // float [4][1024]   16384
constexpr int OFF_PART = 212992;            // float [8][256]     8192
constexpr int OFF_H    = 221184;            // float [256]
constexpr int OFF_C    = 222208;
constexpr int OFF_HC   = 223232;
constexpr int OFF_CTX  = 224256;
constexpr int OFF_GB   = 225280;            // float [1024]  4096
constexpr int OFF_SC   = 229376;            // float [128]
constexpr int OFF_Y    = 229888;            // float [64]
constexpr int OFF_YT   = 230144;            // float [64]
constexpr int OFF_W2   = 230400;            // float [256]
constexpr int OFF_RED  = 231424;            // float [32]
constexpr int SMEM_BYTES = 231552;
}

// fp16 weight copies (converted once per launch)
__device__ __half2 g_whc[D_ * E_];         // [d][c] = (Wh[d][c], Wc[d][c])
__device__ __half  g_whh[D_ * 4 * D_];     // [256][1024]
__device__ __half  g_wih[O_ * 4 * D_];     // [64][1024]
__device__ __half  g_fcwT[O_ * (E_ + O_)]; // [64 cols][320 rows] transposed
__device__ float   g_hctx[B_ * (D_ + E_)];

__device__ __forceinline__ float sigm_f(float x) {
    float e = __expf(-x);
    return __fdividef(1.f, 1.f + e);
}
__device__ __forceinline__ float tanh_f(float x) {
    float e = __expf(2.f * x);
    return 1.f - __fdividef(2.f, e + 1.f);
}
__device__ __forceinline__ void barA() { asm volatile("bar.sync 1, 256;" ::: "memory"); }

__global__ void __launch_bounds__(256) convert_weights_kernel(
    const float* __restrict__ W1, const float* __restrict__ Whh,
    const float* __restrict__ Wih, const float* __restrict__ fcW)
{
    int i = blockIdx.x * 256 + threadIdx.x;
    if (i < D_ * E_) {
        int d = i >> 8, c = i & 255;
        g_whc[i] = __floats2half2_rn(W1[d * E_ + c], W1[(D_ + d) * E_ + c]);
    }
    if (i < D_ * 4 * D_)    g_whh[i] = __float2half_rn(Whh[i]);
    if (i < O_ * 4 * D_)    g_wih[i] = __float2half_rn(Wih[i]);
    if (i < O_ * (E_ + O_)) {
        int c = i / 320, k = i % 320;
        g_fcwT[i] = __float2half_rn(fcW[k * 64 + c]);
    }
}

__global__ void __launch_bounds__(NT, 1) attn_decoder_kernel(
    const float* __restrict__ x, const float* __restrict__ yh,
    const float* __restrict__ h0, const float* __restrict__ c0,
    const float* __restrict__ W1, const float* __restrict__ b1,
    const float* __restrict__ w2, const float* __restrict__ b2,
    const float* __restrict__ bih, const float* __restrict__ bhh,
    const float* __restrict__ fcb)
{
    extern __shared__ char smraw[];
    float*  ep   = (float*)(smraw + OFF_EP);
    __half* x16  = (__half*)(smraw + OFF_X16);
    float*  gsm  = (float*)(smraw + OFF_GS);    // [4][1024]
    float*  part = (float*)(smraw + OFF_PART);  // [8][256]
    float*  hsm  = (float*)(smraw + OFF_H);
    float*  csm  = (float*)(smraw + OFF_C);
    float*  hcsm = (float*)(smraw + OFF_HC);
    float*  ctxs = (float*)(smraw + OFF_CTX);
    float*  gb   = (float*)(smraw + OFF_GB);    // [1024] combined gate bias
    float*  sc   = (float*)(smraw + OFF_SC);
    float*  ysm  = (float*)(smraw + OFF_Y);
    float*  ytl  = (float*)(smraw + OFF_YT);
    float*  w2s  = (float*)(smraw + OFF_W2);
    float*  red  = (float*)(smraw + OFF_RED);

    const int b    = blockIdx.x;
    const int t    = threadIdx.x;
    const int lane = t & 31, w = t >> 5;
    const int r    = t >> 6, j = t & 63;   // hc mapping: 8 groups x 64

    // ---- prologue ----
    const float* xb = x + (size_t)b * S_ * E_;
    for (int i = t; i < S_ * E_; i += NT) x16[i] = __float2half_rn(xb[i]);
    float rb1 = 0.f, rfcb = 0.f;
    if (t < 256) {
        w2s[t] = w2[t];
        hsm[t] = h0[b * D_ + t];
        csm[t] = c0[b * D_ + t];
        rb1 = b1[t];
        float4 a  = ((const float4*)bih)[t];
        float4 c4 = ((const float4*)bhh)[t];
        ((float4*)gb)[t] = make_float4(a.x + c4.x, a.y + c4.y, a.z + c4.z, a.w + c4.w);
        if (t < O_) rfcb = fcb[t];
    }
    const float b2c = b2[0];
    __syncthreads();

    // ---- enc_proj = x[b] @ We  (one-time, fp32 weights) ----
    {
        const float4* We4 = (const float4*)(W1 + 2 * D_ * E_);
        for (int s0 = 16 * r; s0 < 16 * r + 16; s0 += 8) {
            float4 acc[8];
            #pragma unroll
            for (int q = 0; q < 8; q++) acc[q] = make_float4(0.f, 0.f, 0.f, 0.f);
            for (int e = 0; e < E_; e++) {
                float4 wv = We4[e * 64 + j];
                #pragma unroll
                for (int q = 0; q < 8; q++) {
                    float xv = __half2float(x16[(s0 + q) * E_ + e]);
                    acc[q].x = fmaf(xv, wv.x, acc[q].x);
                    acc[q].y = fmaf(xv, wv.y, acc[q].y);
                    acc[q].z = fmaf(xv, wv.z, acc[q].z);
                    acc[q].w = fmaf(xv, wv.w, acc[q].w);
                }
            }
            #pragma unroll
            for (int q = 0; q < 8; q++) ((float4*)(ep + (s0 + q) * E_))[j] = acc[q];
        }
    }
    __syncthreads();

    const uint4* whc4 = (const uint4*)g_whc;   // [256 rows][64 uint4] (4 col-half2)
    const uint4* whh4 = (const uint4*)g_whh;   // [256 rows][128 uint4] (8 cols)
    const uint4* wih4 = (const uint4*)g_wih;   // [64 rows][128 uint4]
    const __half2* x16h2 = (const __half2*)x16;

    for (int step = 0; step < S_; step++) {
        // ===== hc partial: all 512 threads. rows 32r..32r+31, cols 4j..4j+3 =====
        {
            float4 acc = make_float4(0.f, 0.f, 0.f, 0.f);
            const int d0 = 32 * r;
            #pragma unroll
            for (int kk = 0; kk < 32; kk += 8) {
                uint4 v[8];
                #pragma unroll
                for (int q = 0; q < 8; q++) v[q] = whc4[(d0 + kk + q) * 64 + j];
                #pragma unroll
                for (int q = 0; q < 8; q++) {
                    float hv = hsm[d0 + kk + q], cv = csm[d0 + kk + q];
                    float2 p;
                    p = __half22float2(*(__half2*)&v[q].x);
                    acc.x = fmaf(hv, p.x, fmaf(cv, p.y, acc.x));
                    p = __half22float2(*(__half2*)&v[q].y);
                    acc.y = fmaf(hv, p.x, fmaf(cv, p.y, acc.y));
                    p = __half22float2(*(__half2*)&v[q].z);
                    acc.z = fmaf(hv, p.x, fmaf(cv, p.y, acc.z));
                    p = __half22float2(*(__half2*)&v[q].w);
                    acc.w = fmaf(hv, p.x, fmaf(cv, p.y, acc.w));
                }
            }
            ((float4*)(part + r * 256))[j] = acc;
        }
        __syncthreads();   // B1

        if (t < 256) {
            // ================= GROUP A: attention chain =================
            // ysm prefetch + hc reduce
            float yv_ld = 0.f;
            if (t < O_) yv_ld = yh[((size_t)b * S_ + step) * O_ + t];
            {
                float v = rb1;
                #pragma unroll
                for (int rr = 0; rr < 8; rr++) v += part[rr * 256 + t];
                hcsm[t] = v;
                if (t < O_) ysm[t] = yv_ld;
            }
            barA();

            // attention scores: warp w (0..7) handles s = 16w..16w+15
            #pragma unroll 2
            for (int si = 0; si < 16; si++) {
                int   s   = w * 16 + si;
                float sum = 0.f;
                #pragma unroll
                for (int q = 0; q < 8; q++) {
                    int e = lane + 32 * q;
                    sum = fmaf(tanh_f(ep[s * E_ + e] + hcsm[e]), w2s[e], sum);
                }
                #pragma unroll
                for (int off = 16; off; off >>= 1)
                    sum += __shfl_xor_sync(0xffffffffu, sum, off);
                if (lane == 0) sc[s] = sum + b2c;
            }
            barA();

            // softmax by warp 0 alone (each lane owns 4 scores)
            if (w == 0) {
                float v0 = sc[lane], v1 = sc[32 + lane], v2 = sc[64 + lane], v3 = sc[96 + lane];
                float m = fmaxf(fmaxf(v0, v1), fmaxf(v2, v3));
                #pragma unroll
                for (int off = 16; off; off >>= 1)
                    m = fmaxf(m, __shfl_xor_sync(0xffffffffu, m, off));
                float e0 = __expf(v0 - m), e1 = __expf(v1 - m);
                float e2 = __expf(v2 - m), e3 = __expf(v3 - m);
                float s2 = e0 + e1 + e2 + e3;
                #pragma unroll
                for (int off = 16; off; off >>= 1)
                    s2 += __shfl_xor_sync(0xffffffffu, s2, off);
                float inv = __fdividef(1.f, s2);
                sc[lane]      = e0 * inv;
                sc[32 + lane] = e1 * inv;
                sc[64 + lane] = e2 * inv;
                sc[96 + lane] = e3 * inv;
            }
            barA();

            // context: thread (sh = t>>7, e2 = t&127) -> e = 2*e2, s in [64sh,64sh+64)
            {
                const int e2 = t & 127, sh = t >> 7;
                const int s0 = 64 * sh;
                float2 acc2 = make_float2(0.f, 0.f);
                #pragma unroll 8
                for (int s = s0; s < s0 + 64; s++) {
                    float2 xv = __half22float2(x16h2[s * 128 + e2]);
                    float  al = sc[s];
                    acc2.x = fmaf(al, xv.x, acc2.x);
                    acc2.y = fmaf(al, xv.y, acc2.y);
                }
                ((float2*)part)[sh * 128 + e2] = acc2;
            }
            barA();
            if (t < 128) {
                float2 a2 = ((float2*)part)[t];
                float2 b2v = ((float2*)part)[128 + t];
                ((float2*)ctxs)[t] = make_float2(a2.x + b2v.x, a2.y + b2v.y);
            }
            barA();

            // y_tilde: thread (rA = t>>6 in 0..3, j) : k slice [80rA, 80rA+80), col j
            {
                const int rA = t >> 6;
                const uint4* fw4 = (const uint4*)(g_fcwT + j * 320);
                float acc = 0.f;
                #pragma unroll 2
                for (int u = 0; u < 10; u++) {
                    uint4 v = fw4[10 * rA + u];
                    int kb = 80 * rA + 8 * u;
                    #pragma unroll
                    for (int q = 0; q < 4; q++) {
                        float2 p = __half22float2(((__half2*)&v)[q]);
                        int k = kb + 2 * q;
                        float v0 = (k     < E_) ? ctxs[k]     : ysm[k - E_];
                        float v1 = (k + 1 < E_) ? ctxs[k + 1] : ysm[k + 1 - E_];
                        acc = fmaf(v0, p.x, fmaf(v1, p.y, acc));
                    }
                }
                part[512 + t] = acc;
            }
            barA();
            if (t < O_) {
                ytl[t] = rfcb + part[512 + t] + part[576 + t]
                              + part[640 + t] + part[704 + t];
            }
            barA();

            // gates_ih partial: thread (kh2 = t>>7, c8 = t&127): rows 32kh2.., cols 8c8..
            {
                const int c8 = t & 127, kh2 = t >> 7;
                float acc[8];
                #pragma unroll
                for (int i = 0; i < 8; i++) acc[i] = 0.f;
                const int k0b = 32 * kh2;
                #pragma unroll
                for (int kk = 0; kk < 32; kk += 8) {
                    uint4 v[8];
                    #pragma unroll
                    for (int q = 0; q < 8; q++) v[q] = wih4[(k0b + kk + q) * 128 + c8];
                    #pragma unroll
                    for (int q = 0; q < 8; q++) {
                        float yv = ytl[k0b + kk + q];
                        float2 p0 = __half22float2(*(__half2*)&v[q].x);
                        float2 p1 = __half22float2(*(__half2*)&v[q].y);
                        float2 p2 = __half22float2(*(__half2*)&v[q].z);
                        float2 p3 = __half22float2(*(__half2*)&v[q].w);
                        acc[0] = fmaf(yv, p0.x, acc[0]);
                        acc[1] = fmaf(yv, p0.y, acc[1]);
                        acc[2] = fmaf(yv, p1.x, acc[2]);
                        acc[3] = fmaf(yv, p1.y, acc[3]);
                        acc[4] = fmaf(yv, p2.x, acc[4]);
                        acc[5] = fmaf(yv, p2.y, acc[5]);
                        acc[6] = fmaf(yv, p3.x, acc[6]);
                        acc[7] = fmaf(yv, p3.y, acc[7]);
                    }
                }
                float* dst = gsm + (2 + kh2) * 1024 + 8 * c8;
                ((float4*)dst)[0] = make_float4(acc[0], acc[1], acc[2], acc[3]);
                ((float4*)dst)[1] = make_float4(acc[4], acc[5], acc[6], acc[7]);
            }
        } else {
            // ================= GROUP B: gh = h @ Whh =================
            const int tb = t - 256;
            const int c8 = tb & 127, khB = tb >> 7;
            float acc[8];
            #pragma unroll
            for (int i = 0; i < 8; i++) acc[i] = 0.f;
            const int base = 128 * khB;
            #pragma unroll 2
            for (int k0 = 0; k0 < 128; k0 += 8) {
                uint4 v[8];
                #pragma unroll
                for (int q = 0; q < 8; q++) v[q] = whh4[(base + k0 + q) * 128 + c8];
                #pragma unroll
                for (int q = 0; q < 8; q++) {
                    float hv = hsm[base + k0 + q];
                    float2 p0 = __half22float2(*(__half2*)&v[q].x);
                    float2 p1 = __half22float2(*(__half2*)&v[q].y);
                    float2 p2 = __half22float2(*(__half2*)&v[q].z);
                    float2 p3 = __half22float2(*(__half2*)&v[q].w);
                    acc[0] = fmaf(hv, p0.x, acc[0]);
                    acc[1] = fmaf(hv, p0.y, acc[1]);
                    acc[2] = fmaf(hv, p1.x, acc[2]);
                    acc[3] = fmaf(hv, p1.y, acc[3]);
                    acc[4] = fmaf(hv, p2.x, acc[4]);
                    acc[5] = fmaf(hv, p2.y, acc[5]);
                    acc[6] = fmaf(hv, p3.x, acc[6]);
                    acc[7] = fmaf(hv, p3.y, acc[7]);
                }
            }
            float* dst = gsm + khB * 1024 + 8 * c8;
            ((float4*)dst)[0] = make_float4(acc[0], acc[1], acc[2], acc[3]);
            ((float4*)dst)[1] = make_float4(acc[4], acc[5], acc[6], acc[7]);
        }
        __syncthreads();   // B2: gh + gih ready

        // ===== pointwise LSTM update (threads 0..255) =====
        if (t < 256) {
            float gi = gsm[t]        + gsm[1024 + t]        + gsm[2048 + t]        + gsm[3072 + t]        + gb[t];
            float gf = gsm[256 + t]  + gsm[1024 + 256 + t]  + gsm[2048 + 256 + t]  + gsm[3072 + 256 + t]  + gb[256 + t];
            float gg = gsm[512 + t]  + gsm[1024 + 512 + t]  + gsm[2048 + 512 + t]  + gsm[3072 + 512 + t]  + gb[512 + t];
            float go = gsm[768 + t]  + gsm[1024 + 768 + t]  + gsm[2048 + 768 + t]  + gsm[3072 + 768 + t]  + gb[768 + t];
            float cn = fmaf(sigm_f(gf), csm[t], sigm_f(gi) * tanh_f(gg));
            float hn = sigm_f(go) * tanh_f(cn);
            hsm[t] = hn;
            csm[t] = cn;
        }
        __syncthreads();   // B3
    }

    if (t < 256) {
        g_hctx[b * 512 + t]       = hsm[t];
        g_hctx[b * 512 + 256 + t] = ctxs[t];
    }
}

// out[128, 8192] = g_hctx[128,512] @ fc_out_W[512,8192] + b ; 128 blocks, 64-col tiles
__global__ void __launch_bounds__(256, 1) fcout_kernel(
    const float* __restrict__ W, const float* __restrict__ bias,
    float* __restrict__ out)
{
    __shared__ float As[32][128];
    __shared__ float Ws[32][64];
    const int n0 = blockIdx.x * 64;
    const int t  = threadIdx.x;
    const int tx = t & 7, ty = t >> 3;

    float bv[8];
    #pragma unroll
    for (int jj = 0; jj < 8; jj++) bv[jj] = bias[n0 + 8 * tx + jj];

    float acc[4][8];
    #pragma unroll
    for (int i = 0; i < 4; i++)
        #pragma unroll
        for (int jj = 0; jj < 8; jj++) acc[i][jj] = 0.f;

    for (int k0 = 0; k0 < 512; k0 += 32) {
        {
            int q    = t & 7;
            int row0 = t >> 3;
            #pragma unroll
            for (int i = 0; i < 4; i++) {
                int rr = row0 + 32 * i;
                float4 v = *(const float4*)(g_hctx + rr * 512 + k0 + 4 * q);
                As[4 * q + 0][rr] = v.x;
                As[4 * q + 1][rr] = v.y;
                As[4 * q + 2][rr] = v.z;
                As[4 * q + 3][rr] = v.w;
            }
            int nq  = t & 15;
            int kk0 = t >> 4;
            #pragma unroll
            for (int i = 0; i < 2; i++) {
                int kk = kk0 + 16 * i;
                float4 v = *(const float4*)(W + (size_t)(k0 + kk) * 8192 + n0 + 4 * nq);
                *(float4*)(&Ws[kk][4 * nq]) = v;
            }
        }
        __syncthreads();
        #pragma unroll 8
        for (int kk = 0; kk < 32; kk++) {
            float a[4], wv[8];
            #pragma unroll
            for (int i = 0; i < 4; i++) a[i] = As[kk][4 * ty + i];
            #pragma unroll
            for (int jj = 0; jj < 8; jj++) wv[jj] = Ws[kk][8 * tx + jj];
            #pragma unroll
            for (int i = 0; i < 4; i++)
                #pragma unroll
                for (int jj = 0; jj < 8; jj++)
                    acc[i][jj] = fmaf(a[i], wv[jj], acc[i][jj]);
        }
        __syncthreads();
    }
    #pragma unroll
    for (int i = 0; i < 4; i++) {
        int bb = 4 * ty + i;
        #pragma unroll
        for (int jj = 0; jj < 8; jj++)
            out[(size_t)bb * 8192 + n0 + 8 * tx + jj] = acc[i][jj] + bv[jj];
    }
}

extern "C" void kernel_launch(void* const* d_in, const int* in_sizes, int n_in,
                              void* d_out, int out_size)
{
    const float* x   = (const float*)d_in[0];
    const float* yh  = (const float*)d_in[1];
    const float* h0  = (const float*)d_in[2];
    const float* c0  = (const float*)d_in[3];
    const float* W1  = (const float*)d_in[4];
    const float* b1  = (const float*)d_in[5];
    const float* w2  = (const float*)d_in[6];
    const float* b2  = (const float*)d_in[7];
    const float* Wih = (const float*)d_in[8];
    const float* Whh = (const float*)d_in[9];
    const float* bih = (const float*)d_in[10];
    const float* bhh = (const float*)d_in[11];
    const float* fcW = (const float*)d_in[12];
    const float* fcb = (const float*)d_in[13];
    const float* foW = (const float*)d_in[14];
    const float* fob = (const float*)d_in[15];

    convert_weights_kernel<<<(D_ * 4 * D_ + 255) / 256, 256>>>(W1, Whh, Wih, fcW);

    cudaFuncSetAttribute(attn_decoder_kernel,
                         cudaFuncAttributeMaxDynamicSharedMemorySize, SMEM_BYTES);
    attn_decoder_kernel<<<B_, NT, SMEM_BYTES>>>(x, yh, h0, c0, W1, b1, w2, b2,
                                                bih, bhh, fcb);
    fcout_kernel<<<128, 256>>>(foW, fob, (float*)d_out);
}

// round 6
// speedup vs baseline: 2.1865x; 1.1806x over previous
#include <cuda_runtime.h>
#include <cuda_fp16.h>
#include <math.h>

namespace {
constexpr int B_ = 128, S_ = 128, E_ = 256, D_ = 256, O_ = 64;
constexpr int NT = 512;

// dynamic smem layout (bytes)
constexpr int OFF_EP   = 0;                 // float [128][256] 131072
constexpr int OFF_X16  = 131072;            // half  [128][256]  65536
constexpr int OFF_GS   = 196608;            // float [4][1024]   16384
constexpr int OFF_PART = 212992;            // float [8][256]     8192
constexpr int OFF_H    = 221184;            // float [256]
constexpr int OFF_C    = 222208;
constexpr int OFF_HC   = 223232;
constexpr int OFF_CTX  = 224256;
constexpr int OFF_GB   = 225280;            // float [1024]  4096
constexpr int OFF_SC   = 229376;            // float [128]
constexpr int OFF_Y    = 229888;            // float [64]
constexpr int OFF_YT   = 230144;            // float [64]
constexpr int OFF_W2   = 230400;            // float [256]
constexpr int OFF_RED  = 231424;            // float [32]
constexpr int SMEM_BYTES = 231552;
}

// fp16 weight copies (converted once per launch)
__device__ __half2 g_whc[D_ * E_];         // [d][c] = (Wh[d][c], Wc[d][c])
__device__ __half  g_whh[D_ * 4 * D_];     // [256][1024]
__device__ __half  g_wih[O_ * 4 * D_];     // [64][1024]
__device__ __half  g_fcwT[O_ * (E_ + O_)]; // [64 cols][320 rows] transposed
__device__ float   g_hctx[B_ * (D_ + E_)];

__device__ __forceinline__ float sigm_f(float x) {
    float e = __expf(-x);
    return __fdividef(1.f, 1.f + e);
}
__device__ __forceinline__ float tanh_f(float x) {
    float e = __expf(2.f * x);
    return 1.f - __fdividef(2.f, e + 1.f);
}
__device__ __forceinline__ void barA() { asm volatile("bar.sync 1, 256;" ::: "memory"); }
__device__ __forceinline__ void bsync(int id) {
    asm volatile("bar.sync %0, 512;" :: "r"(id) : "memory");
}
__device__ __forceinline__ void barrive(int id) {
    asm volatile("bar.arrive %0, 512;" :: "r"(id) : "memory");
}

__global__ void __launch_bounds__(256) convert_weights_kernel(
    const float* __restrict__ W1, const float* __restrict__ Whh,
    const float* __restrict__ Wih, const float* __restrict__ fcW)
{
    int i = blockIdx.x * 256 + threadIdx.x;
    if (i < D_ * E_) {
        int d = i >> 8, c = i & 255;
        g_whc[i] = __floats2half2_rn(W1[d * E_ + c], W1[(D_ + d) * E_ + c]);
    }
    if (i < D_ * 4 * D_)    g_whh[i] = __float2half_rn(Whh[i]);
    if (i < O_ * 4 * D_)    g_wih[i] = __float2half_rn(Wih[i]);
    if (i < O_ * (E_ + O_)) {
        int c = i / 320, k = i % 320;
        g_fcwT[i] = __float2half_rn(fcW[k * 64 + c]);
    }
}

__global__ void __launch_bounds__(NT, 1) attn_decoder_kernel(
    const float* __restrict__ x, const float* __restrict__ yh,
    const float* __restrict__ h0, const float* __restrict__ c0,
    const float* __restrict__ W1, const float* __restrict__ b1,
    const float* __restrict__ w2, const float* __restrict__ b2,
    const float* __restrict__ bih, const float* __restrict__ bhh,
    const float* __restrict__ fcb)
{
    extern __shared__ char smraw[];
    float*  ep   = (float*)(smraw + OFF_EP);
    __half* x16  = (__half*)(smraw + OFF_X16);
    float*  gsm  = (float*)(smraw + OFF_GS);    // [4][1024]
    float*  part = (float*)(smraw + OFF_PART);  // [8][256]
    float*  hsm  = (float*)(smraw + OFF_H);
    float*  csm  = (float*)(smraw + OFF_C);
    float*  hcsm = (float*)(smraw + OFF_HC);
    float*  ctxs = (float*)(smraw + OFF_CTX);
    float*  gb   = (float*)(smraw + OFF_GB);    // [1024] combined gate bias
    float*  sc   = (float*)(smraw + OFF_SC);
    float*  ysm  = (float*)(smraw + OFF_Y);
    float*  ytl  = (float*)(smraw + OFF_YT);
    float*  w2s  = (float*)(smraw + OFF_W2);

    const int b    = blockIdx.x;
    const int t    = threadIdx.x;
    const int lane = t & 31, w = t >> 5;
    const int r    = t >> 6, j = t & 63;

    // ---- prologue (all 512) ----
    const float* xb = x + (size_t)b * S_ * E_;
    for (int i = t; i < S_ * E_; i += NT) x16[i] = __float2half_rn(xb[i]);
    float rb1 = 0.f, rfcb = 0.f;
    if (t < 256) {
        w2s[t] = w2[t];
        hsm[t] = h0[b * D_ + t];
        csm[t] = c0[b * D_ + t];
        rb1 = b1[t];
        float4 a  = ((const float4*)bih)[t];
        float4 c4 = ((const float4*)bhh)[t];
        ((float4*)gb)[t] = make_float4(a.x + c4.x, a.y + c4.y, a.z + c4.z, a.w + c4.w);
        if (t < O_) rfcb = fcb[t];
    }
    const float b2c = b2[0];
    __syncthreads();

    // ---- enc_proj = x[b] @ We  (one-time, fp32 weights, all 512) ----
    {
        const float4* We4 = (const float4*)(W1 + 2 * D_ * E_);
        for (int s0 = 16 * r; s0 < 16 * r + 16; s0 += 8) {
            float4 acc[8];
            #pragma unroll
            for (int q = 0; q < 8; q++) acc[q] = make_float4(0.f, 0.f, 0.f, 0.f);
            for (int e = 0; e < E_; e++) {
                float4 wv = We4[e * 64 + j];
                #pragma unroll
                for (int q = 0; q < 8; q++) {
                    float xv = __half2float(x16[(s0 + q) * E_ + e]);
                    acc[q].x = fmaf(xv, wv.x, acc[q].x);
                    acc[q].y = fmaf(xv, wv.y, acc[q].y);
                    acc[q].z = fmaf(xv, wv.z, acc[q].z);
                    acc[q].w = fmaf(xv, wv.w, acc[q].w);
                }
            }
            #pragma unroll
            for (int q = 0; q < 8; q++) ((float4*)(ep + (s0 + q) * E_))[j] = acc[q];
        }
    }
    __syncthreads();

    const uint4* whc4 = (const uint4*)g_whc;   // [256 rows][64 uint4]
    const uint4* whh4 = (const uint4*)g_whh;   // [256 rows][128 uint4]
    const uint4* wih4 = (const uint4*)g_wih;   // [64 rows][128 uint4]
    const __half2* x16h2 = (const __half2*)x16;

    if (t < 256) {
        // ==================== GROUP A: compute chain ====================
        barrive(5);   // h0/c0 are ready for group B's first step
        for (int step = 0; step < S_; step++) {
            bsync(3);   // hc partials ready
            float yv_ld = 0.f;
            if (t < O_) yv_ld = yh[((size_t)b * S_ + step) * O_ + t];
            {
                float v = rb1 + part[t] + part[256 + t] + part[512 + t] + part[768 + t];
                hcsm[t] = v;
                if (t < O_) ysm[t] = yv_ld;
            }
            barA();

            // attention scores: warp w (0..7) handles s = 16w..16w+15
            #pragma unroll 2
            for (int si = 0; si < 16; si++) {
                int   s   = w * 16 + si;
                float sum = 0.f;
                #pragma unroll
                for (int q = 0; q < 8; q++) {
                    int e = lane + 32 * q;
                    sum = fmaf(tanh_f(ep[s * E_ + e] + hcsm[e]), w2s[e], sum);
                }
                #pragma unroll
                for (int off = 16; off; off >>= 1)
                    sum += __shfl_xor_sync(0xffffffffu, sum, off);
                if (lane == 0) sc[s] = sum + b2c;
            }
            barA();

            // softmax by warp 0 alone
            if (w == 0) {
                float v0 = sc[lane], v1 = sc[32 + lane], v2 = sc[64 + lane], v3 = sc[96 + lane];
                float m = fmaxf(fmaxf(v0, v1), fmaxf(v2, v3));
                #pragma unroll
                for (int off = 16; off; off >>= 1)
                    m = fmaxf(m, __shfl_xor_sync(0xffffffffu, m, off));
                float e0 = __expf(v0 - m), e1 = __expf(v1 - m);
                float e2 = __expf(v2 - m), e3 = __expf(v3 - m);
                float s2 = e0 + e1 + e2 + e3;
                #pragma unroll
                for (int off = 16; off; off >>= 1)
                    s2 += __shfl_xor_sync(0xffffffffu, s2, off);
                float inv = __fdividef(1.f, s2);
                sc[lane]      = e0 * inv;
                sc[32 + lane] = e1 * inv;
                sc[64 + lane] = e2 * inv;
                sc[96 + lane] = e3 * inv;
            }
            barA();

            // context partials: (sh = t>>7, e2 = t&127)
            {
                const int e2 = t & 127, sh = t >> 7;
                const int s0 = 64 * sh;
                float2 acc2 = make_float2(0.f, 0.f);
                #pragma unroll 8
                for (int s = s0; s < s0 + 64; s++) {
                    float2 xv = __half22float2(x16h2[s * 128 + e2]);
                    float  al = sc[s];
                    acc2.x = fmaf(al, xv.x, acc2.x);
                    acc2.y = fmaf(al, xv.y, acc2.y);
                }
                ((float2*)part)[sh * 128 + e2] = acc2;
            }
            barA();
            if (t < 128) {
                float2 a2  = ((float2*)part)[t];
                float2 b2v = ((float2*)part)[128 + t];
                ((float2*)ctxs)[t] = make_float2(a2.x + b2v.x, a2.y + b2v.y);
            }
            barA();

            // y_tilde: thread (rA = t>>6, j) : k slice [80rA, 80rA+80), col j
            {
                const int rA = t >> 6;
                const uint4* fw4 = (const uint4*)(g_fcwT + j * 320);
                float acc = 0.f;
                #pragma unroll 2
                for (int u = 0; u < 10; u++) {
                    uint4 v = fw4[10 * rA + u];
                    int kb = 80 * rA + 8 * u;
                    #pragma unroll
                    for (int q = 0; q < 4; q++) {
                        float2 p = __half22float2(((__half2*)&v)[q]);
                        int k = kb + 2 * q;
                        float v0 = (k     < E_) ? ctxs[k]     : ysm[k - E_];
                        float v1 = (k + 1 < E_) ? ctxs[k + 1] : ysm[k + 1 - E_];
                        acc = fmaf(v0, p.x, fmaf(v1, p.y, acc));
                    }
                }
                part[512 + t] = acc;
            }
            barA();
            if (t < O_) {
                ytl[t] = rfcb + part[512 + t] + part[576 + t]
                              + part[640 + t] + part[704 + t];
            }
            barrive(6);   // ytl ready for group B's wih stream

            bsync(4);     // all 4 gate partials ready
            {
                float gi = gsm[t]       + gsm[1024 + t]       + gsm[2048 + t]       + gsm[3072 + t]       + gb[t];
                float gf = gsm[256 + t] + gsm[1024 + 256 + t] + gsm[2048 + 256 + t] + gsm[3072 + 256 + t] + gb[256 + t];
                float gg = gsm[512 + t] + gsm[1024 + 512 + t] + gsm[2048 + 512 + t] + gsm[3072 + 512 + t] + gb[512 + t];
                float go = gsm[768 + t] + gsm[1024 + 768 + t] + gsm[2048 + 768 + t] + gsm[3072 + 768 + t] + gb[768 + t];
                float cn = fmaf(sigm_f(gf), csm[t], sigm_f(gi) * tanh_f(gg));
                float hn = sigm_f(go) * tanh_f(cn);
                hsm[t] = hn;
                csm[t] = cn;
            }
            barrive(5);   // new h,c ready for group B
        }

        g_hctx[b * 512 + t]       = hsm[t];
        g_hctx[b * 512 + 256 + t] = ctxs[t];
    } else {
        // ==================== GROUP B: weight streamer ====================
        const int tb  = t - 256;
        const int r2  = tb >> 6, jb = tb & 63;      // hc mapping
        const int c8  = tb & 127, khB = tb >> 7;    // whh/wih mapping

        for (int step = 0; step < S_; step++) {
            bsync(5);   // wait for h,c of this step

            // ---- hc partials: rows 64r2..64r2+63, cols 4jb..4jb+3 ----
            {
                float4 acc = make_float4(0.f, 0.f, 0.f, 0.f);
                const int d0 = 64 * r2;
                #pragma unroll
                for (int kk = 0; kk < 64; kk += 8) {
                    uint4 v[8];
                    #pragma unroll
                    for (int q = 0; q < 8; q++) v[q] = whc4[(d0 + kk + q) * 64 + jb];
                    #pragma unroll
                    for (int q = 0; q < 8; q++) {
                        float hv = hsm[d0 + kk + q], cv = csm[d0 + kk + q];
                        float2 p;
                        p = __half22float2(*(__half2*)&v[q].x);
                        acc.x = fmaf(hv, p.x, fmaf(cv, p.y, acc.x));
                        p = __half22float2(*(__half2*)&v[q].y);
                        acc.y = fmaf(hv, p.x, fmaf(cv, p.y, acc.y));
                        p = __half22float2(*(__half2*)&v[q].z);
                        acc.z = fmaf(hv, p.x, fmaf(cv, p.y, acc.z));
                        p = __half22float2(*(__half2*)&v[q].w);
                        acc.w = fmaf(hv, p.x, fmaf(cv, p.y, acc.w));
                    }
                }
                ((float4*)(part + r2 * 256))[jb] = acc;
            }
            barrive(3);   // hc partials published

            // ---- gh = h @ Whh : k half khB, cols 8c8..8c8+7 -> gsm[0..1] ----
            {
                float acc[8];
                #pragma unroll
                for (int i = 0; i < 8; i++) acc[i] = 0.f;
                const int base = 128 * khB;
                #pragma unroll 2
                for (int k0 = 0; k0 < 128; k0 += 8) {
                    uint4 v[8];
                    #pragma unroll
                    for (int q = 0; q < 8; q++) v[q] = whh4[(base + k0 + q) * 128 + c8];
                    #pragma unroll
                    for (int q = 0; q < 8; q++) {
                        float hv = hsm[base + k0 + q];
                        float2 p0 = __half22float2(*(__half2*)&v[q].x);
                        float2 p1 = __half22float2(*(__half2*)&v[q].y);
                        float2 p2 = __half22float2(*(__half2*)&v[q].z);
                        float2 p3 = __half22float2(*(__half2*)&v[q].w);
                        acc[0] = fmaf(hv, p0.x, acc[0]);
                        acc[1] = fmaf(hv, p0.y, acc[1]);
                        acc[2] = fmaf(hv, p1.x, acc[2]);
                        acc[3] = fmaf(hv, p1.y, acc[3]);
                        acc[4] = fmaf(hv, p2.x, acc[4]);
                        acc[5] = fmaf(hv, p2.y, acc[5]);
                        acc[6] = fmaf(hv, p3.x, acc[6]);
                        acc[7] = fmaf(hv, p3.y, acc[7]);
                    }
                }
                float* dst = gsm + khB * 1024 + 8 * c8;
                ((float4*)dst)[0] = make_float4(acc[0], acc[1], acc[2], acc[3]);
                ((float4*)dst)[1] = make_float4(acc[4], acc[5], acc[6], acc[7]);
            }

            bsync(6);   // wait ytl

            // ---- gih = ytl @ Wih : rows 32khB.., cols 8c8.. -> gsm[2..3] ----
            {
                float acc[8];
                #pragma unroll
                for (int i = 0; i < 8; i++) acc[i] = 0.f;
                const int k0b = 32 * khB;
                #pragma unroll
                for (int kk = 0; kk < 32; kk += 8) {
                    uint4 v[8];
                    #pragma unroll
                    for (int q = 0; q < 8; q++) v[q] = wih4[(k0b + kk + q) * 128 + c8];
                    #pragma unroll
                    for (int q = 0; q < 8; q++) {
                        float yv = ytl[k0b + kk + q];
                        float2 p0 = __half22float2(*(__half2*)&v[q].x);
                        float2 p1 = __half22float2(*(__half2*)&v[q].y);
                        float2 p2 = __half22float2(*(__half2*)&v[q].z);
                        float2 p3 = __half22float2(*(__half2*)&v[q].w);
                        acc[0] = fmaf(yv, p0.x, acc[0]);
                        acc[1] = fmaf(yv, p0.y, acc[1]);
                        acc[2] = fmaf(yv, p1.x, acc[2]);
                        acc[3] = fmaf(yv, p1.y, acc[3]);
                        acc[4] = fmaf(yv, p2.x, acc[4]);
                        acc[5] = fmaf(yv, p2.y, acc[5]);
                        acc[6] = fmaf(yv, p3.x, acc[6]);
                        acc[7] = fmaf(yv, p3.y, acc[7]);
                    }
                }
                float* dst = gsm + (2 + khB) * 1024 + 8 * c8;
                ((float4*)dst)[0] = make_float4(acc[0], acc[1], acc[2], acc[3]);
                ((float4*)dst)[1] = make_float4(acc[4], acc[5], acc[6], acc[7]);
            }
            barrive(4);   // gates published
        }
    }
}

// out[128, 8192] = g_hctx[128,512] @ fc_out_W[512,8192] + b ; 128 blocks, 64-col tiles
__global__ void __launch_bounds__(256, 1) fcout_kernel(
    const float* __restrict__ W, const float* __restrict__ bias,
    float* __restrict__ out)
{
    __shared__ float As[32][128];
    __shared__ float Ws[32][64];
    const int n0 = blockIdx.x * 64;
    const int t  = threadIdx.x;
    const int tx = t & 7, ty = t >> 3;

    float bv[8];
    #pragma unroll
    for (int jj = 0; jj < 8; jj++) bv[jj] = bias[n0 + 8 * tx + jj];

    float acc[4][8];
    #pragma unroll
    for (int i = 0; i < 4; i++)
        #pragma unroll
        for (int jj = 0; jj < 8; jj++) acc[i][jj] = 0.f;

    for (int k0 = 0; k0 < 512; k0 += 32) {
        {
            int q    = t & 7;
            int row0 = t >> 3;
            #pragma unroll
            for (int i = 0; i < 4; i++) {
                int rr = row0 + 32 * i;
                float4 v = *(const float4*)(g_hctx + rr * 512 + k0 + 4 * q);
                As[4 * q + 0][rr] = v.x;
                As[4 * q + 1][rr] = v.y;
                As[4 * q + 2][rr] = v.z;
                As[4 * q + 3][rr] = v.w;
            }
            int nq  = t & 15;
            int kk0 = t >> 4;
            #pragma unroll
            for (int i = 0; i < 2; i++) {
                int kk = kk0 + 16 * i;
                float4 v = *(const float4*)(W + (size_t)(k0 + kk) * 8192 + n0 + 4 * nq);
                *(float4*)(&Ws[kk][4 * nq]) = v;
            }
        }
        __syncthreads();
        #pragma unroll 8
        for (int kk = 0; kk < 32; kk++) {
            float a[4], wv[8];
            #pragma unroll
            for (int i = 0; i < 4; i++) a[i] = As[kk][4 * ty + i];
            #pragma unroll
            for (int jj = 0; jj < 8; jj++) wv[jj] = Ws[kk][8 * tx + jj];
            #pragma unroll
            for (int i = 0; i < 4; i++)
                #pragma unroll
                for (int jj = 0; jj < 8; jj++)
                    acc[i][jj] = fmaf(a[i], wv[jj], acc[i][jj]);
        }
        __syncthreads();
    }
    #pragma unroll
    for (int i = 0; i < 4; i++) {
        int bb = 4 * ty + i;
        #pragma unroll
        for (int jj = 0; jj < 8; jj++)
            out[(size_t)bb * 8192 + n0 + 8 * tx + jj] = acc[i][jj] + bv[jj];
    }
}

extern "C" void kernel_launch(void* const* d_in, const int* in_sizes, int n_in,
                              void* d_out, int out_size)
{
    const float* x   = (const float*)d_in[0];
    const float* yh  = (const float*)d_in[1];
    const float* h0  = (const float*)d_in[2];
    const float* c0  = (const float*)d_in[3];
    const float* W1  = (const float*)d_in[4];
    const float* b1  = (const float*)d_in[5];
    const float* w2  = (const float*)d_in[6];
    const float* b2  = (const float*)d_in[7];
    const float* Wih = (const float*)d_in[8];
    const float* Whh = (const float*)d_in[9];
    const float* bih = (const float*)d_in[10];
    const float* bhh = (const float*)d_in[11];
    const float* fcW = (const float*)d_in[12];
    const float* fcb = (const float*)d_in[13];
    const float* foW = (const float*)d_in[14];
    const float* fob = (const float*)d_in[15];

    convert_weights_kernel<<<(D_ * 4 * D_ + 255) / 256, 256>>>(W1, Whh, Wih, fcW);

    cudaFuncSetAttribute(attn_decoder_kernel,
                         cudaFuncAttributeMaxDynamicSharedMemorySize, SMEM_BYTES);
    attn_decoder_kernel<<<B_, NT, SMEM_BYTES>>>(x, yh, h0, c0, W1, b1, w2, b2,
                                                bih, bhh, fcb);
    fcout_kernel<<<128, 256>>>(foW, fob, (float*)d_out);
}